// round 16
// baseline (speedup 1.0000x reference)
#include <cuda_runtime.h>
#include <cuda_bf16.h>
#include <cuda_fp16.h>
#include <math.h>
#include <stdint.h>

// ---------------------------------------------------------------------------
// Problem constants
// ---------------------------------------------------------------------------
#define BATCH 2
#define SEQ   2048
#define EMBD  1024
#define NHEAD 16
#define HDIM  64
#define MROWS (BATCH * SEQ)          // 4096
#define FFN   (4 * EMBD)             // 4096
#define JOINED 25
#define QKVN  (3 * EMBD)             // 3072

#define WSCALE     1024.0f
#define WSCALE_INV 0.0009765625f

typedef __nv_bfloat16 bf16;
typedef __nv_bfloat162 bf162;

// ---------------------------------------------------------------------------
// Scratch (device globals — no allocation allowed)
// ---------------------------------------------------------------------------
__device__ __align__(128) float g_h1 [MROWS * EMBD];
// fp16 hi/lo activation pairs (GEMM inputs)
__device__ __align__(128) half g_xlnh[MROWS * EMBD];
__device__ __align__(128) half g_xlnl[MROWS * EMBD];
__device__ __align__(128) half g_abh [MROWS * EMBD];
__device__ __align__(128) half g_abl [MROWS * EMBD];
__device__ __align__(128) half g_x2h [MROWS * EMBD];
__device__ __align__(128) half g_x2l [MROWS * EMBD];
__device__ __align__(128) half g_mhh [MROWS * FFN];
__device__ __align__(128) half g_mhl [MROWS * FFN];
// bf16 hi/lo QKV pairs (attention input, bf16x3 path)
__device__ __align__(128) bf16 g_qkvh[MROWS * QKVN];
__device__ __align__(128) bf16 g_qkvl[MROWS * QKVN];
// fp16 transposed weights [N, K], pre-scaled by WSCALE
__device__ __align__(128) half g_wqkvh[QKVN * EMBD];
__device__ __align__(128) half g_wph[EMBD * EMBD];
__device__ __align__(128) half g_w1h[FFN * EMBD];
__device__ __align__(128) half g_w2h[EMBD * FFN];

// ---------------------------------------------------------------------------
// Small helpers
// ---------------------------------------------------------------------------
__device__ __forceinline__ uint32_t smem_to_u32(const void* p) {
    uint32_t a;
    asm("{ .reg .u64 t; cvta.to.shared.u64 t, %1; cvt.u32.u64 %0, t; }"
        : "=r"(a) : "l"(p));
    return a;
}

__device__ __forceinline__ void cp_async16(uint32_t dst, const void* src) {
    asm volatile("cp.async.cg.shared.global [%0], [%1], 16;" :: "r"(dst), "l"(src));
}
__device__ __forceinline__ void cp_commit() {
    asm volatile("cp.async.commit_group;");
}
template <int N>
__device__ __forceinline__ void cp_wait() {
    asm volatile("cp.async.wait_group %0;" :: "n"(N));
}

__device__ __forceinline__ void ldmx4(uint32_t (&r)[4], uint32_t addr) {
    asm volatile("ldmatrix.sync.aligned.m8n8.x4.shared.b16 {%0,%1,%2,%3}, [%4];"
        : "=r"(r[0]), "=r"(r[1]), "=r"(r[2]), "=r"(r[3]) : "r"(addr));
}

__device__ __forceinline__ void ldmx4t(uint32_t (&r)[4], uint32_t addr) {
    asm volatile("ldmatrix.sync.aligned.m8n8.x4.trans.shared.b16 {%0,%1,%2,%3}, [%4];"
        : "=r"(r[0]), "=r"(r[1]), "=r"(r[2]), "=r"(r[3]) : "r"(addr));
}

__device__ __forceinline__ void mma_bf16(float (&d)[4], const uint32_t (&a)[4],
                                         uint32_t b0, uint32_t b1) {
    asm volatile(
        "mma.sync.aligned.m16n8k16.row.col.f32.bf16.bf16.f32 "
        "{%0,%1,%2,%3}, {%4,%5,%6,%7}, {%8,%9}, {%0,%1,%2,%3};"
        : "+f"(d[0]), "+f"(d[1]), "+f"(d[2]), "+f"(d[3])
        : "r"(a[0]), "r"(a[1]), "r"(a[2]), "r"(a[3]), "r"(b0), "r"(b1));
}

__device__ __forceinline__ void mma_fp16(float (&d)[4], const uint32_t (&a)[4],
                                         uint32_t b0, uint32_t b1) {
    asm volatile(
        "mma.sync.aligned.m16n8k16.row.col.f32.f16.f16.f32 "
        "{%0,%1,%2,%3}, {%4,%5,%6,%7}, {%8,%9}, {%0,%1,%2,%3};"
        : "+f"(d[0]), "+f"(d[1]), "+f"(d[2]), "+f"(d[3])
        : "r"(a[0]), "r"(a[1]), "r"(a[2]), "r"(a[3]), "r"(b0), "r"(b1));
}

__device__ __forceinline__ float gelu_exact(float x) {
    return 0.5f * x * (1.0f + erff(x * 0.70710678118654752f));
}

__device__ __forceinline__ void split_bf16(float v, bf16& hi, bf16& lo) {
    hi = __float2bfloat16(v);
    lo = __float2bfloat16(v - __bfloat162float(hi));
}

__device__ __forceinline__ void split_fp16(float v, half& hi, half& lo) {
    hi = __float2half(v);
    lo = __float2half(v - __half2float(hi));
}

__device__ __forceinline__ uint32_t pack_bf162(bf16 a, bf16 b) {
    bf162 t = __halves2bfloat162(a, b);
    uint32_t r;
    memcpy(&r, &t, 4);
    return r;
}

// ---------------------------------------------------------------------------
// Weight prep: W[R,C] fp32 -> WT [C,R] fp16, scaled by WSCALE
// ---------------------------------------------------------------------------
__global__ void wprep_kernel(const float* __restrict__ W, half* __restrict__ Th,
                             int R, int C) {
    __shared__ float t[32][33];
    int c0 = blockIdx.x * 32, r0 = blockIdx.y * 32;
    #pragma unroll
    for (int j = 0; j < 4; j++)
        t[threadIdx.y + j * 8][threadIdx.x] =
            W[(size_t)(r0 + threadIdx.y + j * 8) * C + c0 + threadIdx.x];
    __syncthreads();
    #pragma unroll
    for (int j = 0; j < 4; j++) {
        float v = t[threadIdx.x][threadIdx.y + j * 8] * WSCALE;
        size_t idx = (size_t)(c0 + threadIdx.y + j * 8) * R + r0 + threadIdx.x;
        Th[idx] = __float2half(v);
    }
}

__global__ void wprep3_kernel(const float* __restrict__ Wq,
                              const float* __restrict__ Wk,
                              const float* __restrict__ Wv,
                              half* __restrict__ Th) {
    __shared__ float t[32][33];
    const float* W = (blockIdx.z == 0) ? Wq : ((blockIdx.z == 1) ? Wk : Wv);
    half* Tho = Th + (size_t)blockIdx.z * EMBD * EMBD;
    int c0 = blockIdx.x * 32, r0 = blockIdx.y * 32;
    #pragma unroll
    for (int j = 0; j < 4; j++)
        t[threadIdx.y + j * 8][threadIdx.x] =
            W[(size_t)(r0 + threadIdx.y + j * 8) * EMBD + c0 + threadIdx.x];
    __syncthreads();
    #pragma unroll
    for (int j = 0; j < 4; j++) {
        float v = t[threadIdx.x][threadIdx.y + j * 8] * WSCALE;
        size_t idx = (size_t)(c0 + threadIdx.y + j * 8) * EMBD + r0 + threadIdx.x;
        Tho[idx] = __float2half(v);
    }
}

// ---------------------------------------------------------------------------
// LayerNorm -> fp16 hi/lo pair
// ---------------------------------------------------------------------------
__global__ void ln_pair_kernel(const float* __restrict__ x,
                               const float* __restrict__ g,
                               const float* __restrict__ beta,
                               half* __restrict__ yh, half* __restrict__ yl) {
    int row = blockIdx.x;
    int tid = threadIdx.x;
    const float4* xr = (const float4*)(x + (size_t)row * EMBD);
    float4 v = xr[tid];
    float s  = v.x + v.y + v.z + v.w;
    float ss = v.x*v.x + v.y*v.y + v.z*v.z + v.w*v.w;
    #pragma unroll
    for (int o = 16; o > 0; o >>= 1) {
        s  += __shfl_xor_sync(0xffffffffu, s,  o);
        ss += __shfl_xor_sync(0xffffffffu, ss, o);
    }
    __shared__ float sh[16];
    __shared__ float mean_s, rstd_s;
    int wid = tid >> 5, lane = tid & 31;
    if (lane == 0) { sh[wid] = s; sh[wid + 8] = ss; }
    __syncthreads();
    if (tid == 0) {
        float ts = 0.f, tss = 0.f;
        #pragma unroll
        for (int i = 0; i < 8; i++) { ts += sh[i]; tss += sh[i + 8]; }
        float mean = ts * (1.0f / EMBD);
        float var  = tss * (1.0f / EMBD) - mean * mean;
        mean_s = mean;
        rstd_s = rsqrtf(var + 1e-5f);
    }
    __syncthreads();
    float mean = mean_s, rstd = rstd_s;
    float4 gv = ((const float4*)g)[tid];
    float4 bv = ((const float4*)beta)[tid];
    float o[4];
    o[0] = (v.x - mean) * rstd * gv.x + bv.x;
    o[1] = (v.y - mean) * rstd * gv.y + bv.y;
    o[2] = (v.z - mean) * rstd * gv.z + bv.z;
    o[3] = (v.w - mean) * rstd * gv.w + bv.w;
    half2* yh2 = (half2*)(yh + (size_t)row * EMBD);
    half2* yl2 = (half2*)(yl + (size_t)row * EMBD);
    #pragma unroll
    for (int p = 0; p < 2; p++) {
        half h0, l0, h1, l1;
        split_fp16(o[p * 2 + 0], h0, l0);
        split_fp16(o[p * 2 + 1], h1, l1);
        yh2[tid * 2 + p] = __halves2half2(h0, h1);
        yl2[tid * 2 + p] = __halves2half2(l0, l1);
    }
}

// ---------------------------------------------------------------------------
// fp16x2 mma.sync GEMM — D = Ah*Bh + Al*Bh.
// BK=64, 2-stage, ONE barrier per BK=64 k-tile (16 barriers at K=1024),
// classic SW128 swizzle on full 128B rows, 98304 B smem -> 2 CTAs/SM.
// ---------------------------------------------------------------------------
#define EPI_GELU 1
#define EPI_ADD  2
#define EPI_QKV  4

#define TILE_B 16384                  // 128 rows x 128B
#define OFF_AH 0
#define OFF_AL (1 * TILE_B)
#define OFF_BH (2 * TILE_B)
#define STAGE_B (3 * TILE_B)          // 49152
#define GEMM_SMEM (2 * STAGE_B)       // 98304

// SW128: row r (128B), 16B chunk c in 0..7 -> offset r*128 + ((c ^ (r&7))<<4)
__device__ __forceinline__ void load_stage(
    uint32_t sdst, const half* __restrict__ Ah, const half* __restrict__ Al,
    const half* __restrict__ Bh,
    int row0, int col0, int k0, int K, int tid) {
    int r  = tid >> 1;            // 0..127
    int c2 = (tid & 1) * 4;       // first chunk of this thread's 64B half
    int rx = r & 7;
    size_t a = (size_t)(row0 + r) * K + k0 + c2 * 8;
    size_t b = (size_t)(col0 + r) * K + k0 + c2 * 8;
    uint32_t rb = sdst + r * 128;
    #pragma unroll
    for (int i = 0; i < 4; i++) {
        uint32_t d = rb + (((c2 + i) ^ rx) << 4);
        cp_async16(d + OFF_AH, Ah + a + i * 8);
        cp_async16(d + OFF_AL, Al + a + i * 8);
        cp_async16(d + OFF_BH, Bh + b + i * 8);
    }
}

template <int EPI>
__global__ void __launch_bounds__(256, 2)
mma_gemm(const half* __restrict__ Ah, const half* __restrict__ Al,
         const half* __restrict__ Bh,
         const float* __restrict__ bias, const float* __restrict__ biasK,
         const float* __restrict__ biasV, const float* __restrict__ add,
         float* __restrict__ Cf, void* Chi_, void* Clo_,
         int M, int N, int K) {
    extern __shared__ char smem[];
    const uint32_t sb = smem_to_u32(smem);
    const int tid  = threadIdx.x;
    const int lane = tid & 31;
    const int warp = tid >> 5;
    const int wm = warp >> 2;
    const int wn = warp & 3;
    const int row0 = blockIdx.y * 128;
    const int col0 = blockIdx.x * 128;

    float acc[4][4][4];
    #pragma unroll
    for (int m = 0; m < 4; m++)
        #pragma unroll
        for (int n = 0; n < 4; n++)
            #pragma unroll
            for (int e = 0; e < 4; e++) acc[m][n][e] = 0.f;

    const int KT = K / 64;

    load_stage(sb, Ah, Al, Bh, row0, col0, 0, K, tid);
    cp_commit();

    // Per-lane ldmatrix bases. A: rows wm*64 + (lane&15) (+16m); chunk 2ks+(lane>>4).
    const int arow = wm * 64 + (lane & 15);
    const uint32_t a_rb = (uint32_t)(arow << 7);
    const uint32_t a_rx = (uint32_t)(arow & 7);
    const uint32_t a_c0 = (uint32_t)(lane >> 4);

    const int brow = wn * 32 + ((lane >> 4) << 3) + (lane & 7);
    const uint32_t b_rb = (uint32_t)(brow << 7);
    const uint32_t b_rx = (uint32_t)(brow & 7);
    const uint32_t b_c0 = (uint32_t)((lane >> 3) & 1);

    for (int kt = 0; kt < KT; kt++) {
        cp_wait<0>();
        __syncthreads();
        if (kt + 1 < KT) {
            load_stage(sb + ((kt + 1) & 1) * STAGE_B, Ah, Al, Bh,
                       row0, col0, (kt + 1) * 64, K, tid);
            cp_commit();
        }

        uint32_t s = sb + (kt & 1) * STAGE_B;
        #pragma unroll
        for (int ks = 0; ks < 4; ks++) {
            const uint32_t aoff = a_rb + ((((2 * ks) + a_c0) ^ a_rx) << 4);
            const uint32_t boff = b_rb + ((((2 * ks) + b_c0) ^ b_rx) << 4);
            uint32_t ah[4][4], al[4][4], bh[2][4];
            #pragma unroll
            for (int m = 0; m < 4; m++)
                ldmx4(ah[m], s + OFF_AH + aoff + m * 2048);
            #pragma unroll
            for (int m = 0; m < 4; m++)
                ldmx4(al[m], s + OFF_AL + aoff + m * 2048);
            #pragma unroll
            for (int n2 = 0; n2 < 2; n2++)
                ldmx4(bh[n2], s + OFF_BH + boff + n2 * 2048);

            #pragma unroll
            for (int m = 0; m < 4; m++)
                #pragma unroll
                for (int n = 0; n < 4; n++)
                    mma_fp16(acc[m][n], ah[m], bh[n >> 1][(n & 1) * 2],
                                               bh[n >> 1][(n & 1) * 2 + 1]);
            #pragma unroll
            for (int m = 0; m < 4; m++)
                #pragma unroll
                for (int n = 0; n < 4; n++)
                    mma_fp16(acc[m][n], al[m], bh[n >> 1][(n & 1) * 2],
                                               bh[n >> 1][(n & 1) * 2 + 1]);
        }
    }

    // Epilogue (acc carries WSCALE; undo before bias)
    const float* bseg = bias;
    int csub = 0;
    float scale = 1.0f;
    if (EPI == EPI_QKV) {
        int seg = col0 >> 10;
        bseg = (seg == 0) ? bias : ((seg == 1) ? biasK : biasV);
        csub = seg << 10;
        scale = (seg == 0) ? 0.125f : 1.0f;
    }
    const int erow = row0 + wm * 64 + (lane >> 2);
    const int ecol = col0 + wn * 32 + (lane & 3) * 2;
    #pragma unroll
    for (int m = 0; m < 4; m++) {
        #pragma unroll
        for (int n = 0; n < 4; n++) {
            int c = ecol + n * 8;
            float b0 = bseg[c - csub], b1 = bseg[c - csub + 1];
            #pragma unroll
            for (int half_i = 0; half_i < 2; half_i++) {
                int r = erow + m * 16 + half_i * 8;
                float v0 = acc[m][n][half_i * 2 + 0] * WSCALE_INV + b0;
                float v1 = acc[m][n][half_i * 2 + 1] * WSCALE_INV + b1;
                if (EPI == EPI_ADD) {
                    const float2 av = *(const float2*)&add[(size_t)r * N + c];
                    v0 += av.x; v1 += av.y;
                    float2 o; o.x = v0; o.y = v1;
                    *(float2*)&Cf[(size_t)r * N + c] = o;
                } else if (EPI == EPI_QKV) {
                    v0 *= scale;
                    v1 *= scale;
                    bf16 h0, l0, h1, l1;
                    split_bf16(v0, h0, l0);
                    split_bf16(v1, h1, l1);
                    bf16* Chi = (bf16*)Chi_;
                    bf16* Clo = (bf16*)Clo_;
                    *(bf162*)&Chi[(size_t)r * N + c] = __halves2bfloat162(h0, h1);
                    *(bf162*)&Clo[(size_t)r * N + c] = __halves2bfloat162(l0, l1);
                } else {   // EPI_GELU
                    v0 = gelu_exact(v0);
                    v1 = gelu_exact(v1);
                    half h0, l0, h1, l1;
                    split_fp16(v0, h0, l0);
                    split_fp16(v1, h1, l1);
                    half* Chi = (half*)Chi_;
                    half* Clo = (half*)Clo_;
                    *(half2*)&Chi[(size_t)r * N + c] = __halves2half2(h0, h1);
                    *(half2*)&Clo[(size_t)r * N + c] = __halves2half2(l0, l1);
                }
            }
        }
    }
}

// ---------------------------------------------------------------------------
// Flash attention (bf16x3 internally), reading fused QKV bf16 pairs,
// writing fp16 pairs for the projection GEMM.
// ---------------------------------------------------------------------------
#define AT_TROW 144
#define AT_QH   0
#define AT_QL   9216
#define AT_KV0  18432
#define AT_STAGE 36864
#define AT_SMEM (18432 + 2 * 36864)   // 92160

__device__ __forceinline__ void attn_load_kv(
    uint32_t sb, int b, int h, const bf16* __restrict__ QKVh,
    const bf16* __restrict__ QKVl, int kt, int stage, int tid) {
    int kb = kt * 64;
    #pragma unroll
    for (int i = 0; i < 4; i++) {
        int c = tid + i * 128;
        int r = c >> 3, sg = c & 7;
        size_t g = (size_t)(b * SEQ + kb + r) * QKVN + h * HDIM + sg * 8;
        uint32_t d = sb + AT_KV0 + stage * AT_STAGE + r * AT_TROW + sg * 16;
        cp_async16(d,             QKVh + g + EMBD);
        cp_async16(d + 9216,      QKVl + g + EMBD);
        cp_async16(d + 18432,     QKVh + g + 2 * EMBD);
        cp_async16(d + 27648,     QKVl + g + 2 * EMBD);
    }
}

__global__ void __launch_bounds__(128)
fattn_kernel(const bf16* __restrict__ QKVh, const bf16* __restrict__ QKVl,
             half* __restrict__ Oh, half* __restrict__ Ol) {
    extern __shared__ char smem[];
    const uint32_t sb = smem_to_u32(smem);
    const int tid = threadIdx.x;
    const int lane = tid & 31;
    const int wm = tid >> 5;
    const int qt = blockIdx.x;
    const int h  = blockIdx.y;
    const int b  = blockIdx.z;
    const int q0 = qt * 64;
    const int qrow0 = q0 + wm * 16 + (lane >> 2);
    const int qrow1 = qrow0 + 8;

    #pragma unroll
    for (int i = 0; i < 4; i++) {
        int c = tid + i * 128;
        int r = c >> 3, sg = c & 7;
        size_t g = (size_t)(b * SEQ + q0 + r) * QKVN + h * HDIM + sg * 8;
        cp_async16(sb + AT_QH + r * AT_TROW + sg * 16, QKVh + g);
        cp_async16(sb + AT_QL + r * AT_TROW + sg * 16, QKVl + g);
    }
    attn_load_kv(sb, b, h, QKVh, QKVl, 0, 0, tid);
    cp_commit();

    float m0 = -1e30f, m1 = -1e30f, l0 = 0.f, l1 = 0.f;
    float acc[8][4];
    #pragma unroll
    for (int j = 0; j < 8; j++)
        #pragma unroll
        for (int e = 0; e < 4; e++) acc[j][e] = 0.f;

    uint32_t qhf[4][4], qlf[4][4];
    const int ntiles = qt + 1;
    const int ce = (lane & 3) * 2;

    for (int kt = 0; kt < ntiles; kt++) {
        if (kt + 1 < ntiles) {
            attn_load_kv(sb, b, h, QKVh, QKVl, kt + 1, (kt + 1) & 1, tid);
            cp_commit();
            cp_wait<1>();
        } else {
            cp_wait<0>();
        }
        __syncthreads();

        if (kt == 0) {
            uint32_t qa = sb + AT_QH + (wm * 16 + (lane & 15)) * AT_TROW + (lane >> 4) * 16;
            #pragma unroll
            for (int ks = 0; ks < 4; ks++) {
                ldmx4(qhf[ks], qa + ks * 32);
                ldmx4(qlf[ks], qa + 9216 + ks * 32);
            }
        }

        const uint32_t sK = sb + AT_KV0 + (kt & 1) * AT_STAGE;
        const uint32_t sV = sK + 18432;

        float c[8][4];
        #pragma unroll
        for (int j = 0; j < 8; j++)
            #pragma unroll
            for (int e = 0; e < 4; e++) c[j][e] = 0.f;

        const uint32_t bb = (((lane >> 4) << 3) + (lane & 7)) * AT_TROW
                            + ((lane >> 3) & 1) * 16;
        #pragma unroll
        for (int ks = 0; ks < 4; ks++) {
            uint32_t kbh[4][4], kbl[4][4];
            #pragma unroll
            for (int nn = 0; nn < 4; nn++) {
                ldmx4(kbh[nn], sK + nn * 16 * AT_TROW + bb + ks * 32);
                ldmx4(kbl[nn], sK + 9216 + nn * 16 * AT_TROW + bb + ks * 32);
            }
            #pragma unroll
            for (int j = 0; j < 8; j++) {
                uint32_t h0 = kbh[j >> 1][(j & 1) * 2], h1 = kbh[j >> 1][(j & 1) * 2 + 1];
                uint32_t lo0 = kbl[j >> 1][(j & 1) * 2], lo1 = kbl[j >> 1][(j & 1) * 2 + 1];
                mma_bf16(c[j], qhf[ks], h0, h1);
                mma_bf16(c[j], qhf[ks], lo0, lo1);
                mma_bf16(c[j], qlf[ks], h0, h1);
            }
        }

        const int kb = kt * 64;
        float tmax0 = -1e30f, tmax1 = -1e30f;
        #pragma unroll
        for (int j = 0; j < 8; j++) {
            int ka = kb + j * 8 + ce;
            int kc = ka + 1;
            bool okA = ((ka + 1) % JOINED != 0);
            bool okB = ((kc + 1) % JOINED != 0);
            float s0 = (okA && ka <= qrow0) ? c[j][0] : -1e30f;
            float s1 = (okB && kc <= qrow0) ? c[j][1] : -1e30f;
            float s2 = (okA && ka <= qrow1) ? c[j][2] : -1e30f;
            float s3 = (okB && kc <= qrow1) ? c[j][3] : -1e30f;
            c[j][0] = s0; c[j][1] = s1; c[j][2] = s2; c[j][3] = s3;
            tmax0 = fmaxf(tmax0, fmaxf(s0, s1));
            tmax1 = fmaxf(tmax1, fmaxf(s2, s3));
        }
        tmax0 = fmaxf(tmax0, __shfl_xor_sync(0xffffffffu, tmax0, 1));
        tmax0 = fmaxf(tmax0, __shfl_xor_sync(0xffffffffu, tmax0, 2));
        tmax1 = fmaxf(tmax1, __shfl_xor_sync(0xffffffffu, tmax1, 1));
        tmax1 = fmaxf(tmax1, __shfl_xor_sync(0xffffffffu, tmax1, 2));
        float mn0 = fmaxf(m0, tmax0), mn1 = fmaxf(m1, tmax1);
        float cr0 = __expf(m0 - mn0), cr1 = __expf(m1 - mn1);
        m0 = mn0; m1 = mn1;

        uint32_t pah[4][4], pal[4][4];
        float ps0 = 0.f, ps1 = 0.f;
        #pragma unroll
        for (int j = 0; j < 8; j++) {
            float p0 = __expf(c[j][0] - mn0);
            float p1 = __expf(c[j][1] - mn0);
            float p2 = __expf(c[j][2] - mn1);
            float p3 = __expf(c[j][3] - mn1);
            ps0 += p0 + p1;
            ps1 += p2 + p3;
            bf16 h0, lo0, h1, lo1, h2, lo2, h3, lo3;
            split_bf16(p0, h0, lo0); split_bf16(p1, h1, lo1);
            split_bf16(p2, h2, lo2); split_bf16(p3, h3, lo3);
            int t = j >> 1, rr = (j & 1) * 2;
            pah[t][rr]     = pack_bf162(h0, h1);
            pah[t][rr + 1] = pack_bf162(h2, h3);
            pal[t][rr]     = pack_bf162(lo0, lo1);
            pal[t][rr + 1] = pack_bf162(lo2, lo3);
        }
        l0 = l0 * cr0 + ps0;
        l1 = l1 * cr1 + ps1;
        #pragma unroll
        for (int j = 0; j < 8; j++) {
            acc[j][0] *= cr0; acc[j][1] *= cr0;
            acc[j][2] *= cr1; acc[j][3] *= cr1;
        }

        const uint32_t vrow = (lane & 7) + ((lane >> 3) & 1) * 8;
        const uint32_t vcb  = (lane >> 4) * 16;
        #pragma unroll
        for (int t = 0; t < 4; t++) {
            uint32_t vbh[4][4], vbl[4][4];
            uint32_t vb = sV + (t * 16 + vrow) * AT_TROW + vcb;
            #pragma unroll
            for (int jj = 0; jj < 4; jj++) {
                ldmx4t(vbh[jj], vb + jj * 32);
                ldmx4t(vbl[jj], vb + 9216 + jj * 32);
            }
            #pragma unroll
            for (int jj = 0; jj < 4; jj++) {
                mma_bf16(acc[2 * jj],     pah[t], vbh[jj][0], vbh[jj][1]);
                mma_bf16(acc[2 * jj + 1], pah[t], vbh[jj][2], vbh[jj][3]);
                mma_bf16(acc[2 * jj],     pal[t], vbh[jj][0], vbh[jj][1]);
                mma_bf16(acc[2 * jj + 1], pal[t], vbh[jj][2], vbh[jj][3]);
                mma_bf16(acc[2 * jj],     pah[t], vbl[jj][0], vbl[jj][1]);
                mma_bf16(acc[2 * jj + 1], pah[t], vbl[jj][2], vbl[jj][3]);
            }
        }
        __syncthreads();
    }

    l0 += __shfl_xor_sync(0xffffffffu, l0, 1);
    l0 += __shfl_xor_sync(0xffffffffu, l0, 2);
    l1 += __shfl_xor_sync(0xffffffffu, l1, 1);
    l1 += __shfl_xor_sync(0xffffffffu, l1, 2);
    float inv0 = 1.0f / l0, inv1 = 1.0f / l1;
    size_t o0 = (size_t)(b * SEQ + qrow0) * EMBD + h * HDIM;
    size_t o1 = (size_t)(b * SEQ + qrow1) * EMBD + h * HDIM;
    #pragma unroll
    for (int j = 0; j < 8; j++) {
        int cc = j * 8 + ce;
        float v0 = acc[j][0] * inv0, v1 = acc[j][1] * inv0;
        float v2 = acc[j][2] * inv1, v3 = acc[j][3] * inv1;
        half h0, lo0, h1, lo1, h2, lo2, h3, lo3;
        split_fp16(v0, h0, lo0); split_fp16(v1, h1, lo1);
        split_fp16(v2, h2, lo2); split_fp16(v3, h3, lo3);
        *(half2*)&Oh[o0 + cc] = __halves2half2(h0, h1);
        *(half2*)&Ol[o0 + cc] = __halves2half2(lo0, lo1);
        *(half2*)&Oh[o1 + cc] = __halves2half2(h2, h3);
        *(half2*)&Ol[o1 + cc] = __halves2half2(lo2, lo3);
    }
}

// ---------------------------------------------------------------------------
// Host launcher
// ---------------------------------------------------------------------------
extern "C" void kernel_launch(void* const* d_in, const int* in_sizes, int n_in,
                              void* d_out, int out_size) {
    const float* hidden = (const float*)d_in[0];
    const float* Wq = (const float*)d_in[1];
    const float* bq = (const float*)d_in[2];
    const float* Wk = (const float*)d_in[3];
    const float* bk = (const float*)d_in[4];
    const float* Wv = (const float*)d_in[5];
    const float* bv = (const float*)d_in[6];
    const float* Wp = (const float*)d_in[7];
    const float* bp = (const float*)d_in[8];
    const float* ln1_g = (const float*)d_in[9];
    const float* ln1_b = (const float*)d_in[10];
    const float* ln2_g = (const float*)d_in[11];
    const float* ln2_b = (const float*)d_in[12];
    const float* W1 = (const float*)d_in[13];
    const float* b1 = (const float*)d_in[14];
    const float* W2 = (const float*)d_in[15];
    const float* b2 = (const float*)d_in[16];
    float* out = (float*)d_out;

    float *h1;
    half *xlnh, *xlnl, *abh, *abl, *x2h, *x2l, *mhh, *mhl;
    half *wqkvh, *wph, *w1h, *w2h;
    bf16 *qkvh, *qkvl;
    cudaGetSymbolAddress((void**)&h1,  g_h1);
    cudaGetSymbolAddress((void**)&xlnh, g_xlnh);
    cudaGetSymbolAddress((void**)&xlnl, g_xlnl);
    cudaGetSymbolAddress((void**)&qkvh, g_qkvh);
    cudaGetSymbolAddress((void**)&qkvl, g_qkvl);
    cudaGetSymbolAddress((void**)&abh, g_abh);
    cudaGetSymbolAddress((void**)&abl, g_abl);
    cudaGetSymbolAddress((void**)&x2h, g_x2h);
    cudaGetSymbolAddress((void**)&x2l, g_x2l);
    cudaGetSymbolAddress((void**)&mhh, g_mhh);
    cudaGetSymbolAddress((void**)&mhl, g_mhl);
    cudaGetSymbolAddress((void**)&wqkvh, g_wqkvh);
    cudaGetSymbolAddress((void**)&wph, g_wph);
    cudaGetSymbolAddress((void**)&w1h, g_w1h);
    cudaGetSymbolAddress((void**)&w2h, g_w2h);

    cudaFuncSetAttribute(mma_gemm<EPI_QKV>,
                         cudaFuncAttributeMaxDynamicSharedMemorySize, GEMM_SMEM);
    cudaFuncSetAttribute(mma_gemm<EPI_ADD>,
                         cudaFuncAttributeMaxDynamicSharedMemorySize, GEMM_SMEM);
    cudaFuncSetAttribute(mma_gemm<EPI_GELU>,
                         cudaFuncAttributeMaxDynamicSharedMemorySize, GEMM_SMEM);
    cudaFuncSetAttribute(fattn_kernel,
                         cudaFuncAttributeMaxDynamicSharedMemorySize, AT_SMEM);

    dim3 tb(32, 8);

    // 0. LN1
    ln_pair_kernel<<<MROWS, 256>>>(hidden, ln1_g, ln1_b, xlnh, xlnl);

    // 1. Fused QKV weight prep (fp16, scaled)
    wprep3_kernel<<<dim3(EMBD/32, EMBD/32, 3), tb>>>(Wq, Wk, Wv, wqkvh);

    // 2. Wp prep
    wprep_kernel<<<dim3(EMBD/32, EMBD/32), tb>>>(Wp, wph, EMBD, EMBD);

    // 3. Fused QKV projection -> bf16 pairs (Q pre-scaled 1/8)
    dim3 grid_qkv(QKVN / 128, MROWS / 128);
    mma_gemm<EPI_QKV><<<grid_qkv, 256, GEMM_SMEM>>>(xlnh, xlnl, wqkvh,
                                                    bq, bk, bv, nullptr,
                                                    nullptr, qkvh, qkvl,
                                                    MROWS, QKVN, EMBD);

    // 4. Flash attention -> fp16 pairs
    dim3 agrid(SEQ / 64, NHEAD, BATCH);
    fattn_kernel<<<agrid, 128, AT_SMEM>>>(qkvh, qkvl, abh, abl);

    // 5. Output projection + residual -> h1 (fp32)
    dim3 grid_d(EMBD / 128, MROWS / 128);
    mma_gemm<EPI_ADD><<<grid_d, 256, GEMM_SMEM>>>(abh, abl, wph,
                                                  bp, nullptr, nullptr, hidden,
                                                  h1, nullptr, nullptr,
                                                  MROWS, EMBD, EMBD);

    // 6-7. MLP weight preps
    wprep_kernel<<<dim3(FFN/32,  EMBD/32), tb>>>(W1, w1h, EMBD, FFN);
    wprep_kernel<<<dim3(EMBD/32, FFN/32),  tb>>>(W2, w2h, FFN, EMBD);

    // 8. LN2
    ln_pair_kernel<<<MROWS, 256>>>(h1, ln2_g, ln2_b, x2h, x2l);

    // 9. MLP up + GELU -> fp16 pairs
    dim3 grid_f(FFN / 128, MROWS / 128);
    mma_gemm<EPI_GELU><<<grid_f, 256, GEMM_SMEM>>>(x2h, x2l, w1h,
                                                   b1, nullptr, nullptr, nullptr,
                                                   nullptr, mhh, mhl,
                                                   MROWS, FFN, EMBD);

    // 10. MLP down + residual2 -> out
    mma_gemm<EPI_ADD><<<grid_d, 256, GEMM_SMEM>>>(mhh, mhl, w2h,
                                                  b2, nullptr, nullptr, h1,
                                                  out, nullptr, nullptr,
                                                  MROWS, EMBD, FFN);
}

// round 17
// speedup vs baseline: 1.2742x; 1.2742x over previous
#include <cuda_runtime.h>
#include <cuda_bf16.h>
#include <cuda_fp16.h>
#include <math.h>
#include <stdint.h>

// ---------------------------------------------------------------------------
// Problem constants
// ---------------------------------------------------------------------------
#define BATCH 2
#define SEQ   2048
#define EMBD  1024
#define NHEAD 16
#define HDIM  64
#define MROWS (BATCH * SEQ)          // 4096
#define FFN   (4 * EMBD)             // 4096
#define JOINED 25
#define QKVN  (3 * EMBD)             // 3072

#define WSCALE     1024.0f
#define WSCALE_INV 0.0009765625f

typedef __nv_bfloat16 bf16;
typedef __nv_bfloat162 bf162;

// ---------------------------------------------------------------------------
// Scratch (device globals — no allocation allowed)
// ---------------------------------------------------------------------------
__device__ __align__(128) float g_h1 [MROWS * EMBD];
// fp16 hi/lo activation pairs (GEMM inputs)
__device__ __align__(128) half g_xlnh[MROWS * EMBD];
__device__ __align__(128) half g_xlnl[MROWS * EMBD];
__device__ __align__(128) half g_abh [MROWS * EMBD];
__device__ __align__(128) half g_abl [MROWS * EMBD];
__device__ __align__(128) half g_x2h [MROWS * EMBD];
__device__ __align__(128) half g_x2l [MROWS * EMBD];
__device__ __align__(128) half g_mhh [MROWS * FFN];
__device__ __align__(128) half g_mhl [MROWS * FFN];
// fp16 attention operands: Q hi/lo pair, K single, V single
__device__ __align__(128) half g_qh [MROWS * EMBD];
__device__ __align__(128) half g_ql [MROWS * EMBD];
__device__ __align__(128) half g_kh [MROWS * EMBD];
__device__ __align__(128) half g_vh [MROWS * EMBD];
// fp16 transposed weights [N, K], pre-scaled by WSCALE
__device__ __align__(128) half g_wqkvh[QKVN * EMBD];
__device__ __align__(128) half g_wph[EMBD * EMBD];
__device__ __align__(128) half g_w1h[FFN * EMBD];
__device__ __align__(128) half g_w2h[EMBD * FFN];

// ---------------------------------------------------------------------------
// Small helpers
// ---------------------------------------------------------------------------
__device__ __forceinline__ uint32_t smem_to_u32(const void* p) {
    uint32_t a;
    asm("{ .reg .u64 t; cvta.to.shared.u64 t, %1; cvt.u32.u64 %0, t; }"
        : "=r"(a) : "l"(p));
    return a;
}

__device__ __forceinline__ void cp_async16(uint32_t dst, const void* src) {
    asm volatile("cp.async.cg.shared.global [%0], [%1], 16;" :: "r"(dst), "l"(src));
}
__device__ __forceinline__ void cp_commit() {
    asm volatile("cp.async.commit_group;");
}
template <int N>
__device__ __forceinline__ void cp_wait() {
    asm volatile("cp.async.wait_group %0;" :: "n"(N));
}

__device__ __forceinline__ void ldmx4(uint32_t (&r)[4], uint32_t addr) {
    asm volatile("ldmatrix.sync.aligned.m8n8.x4.shared.b16 {%0,%1,%2,%3}, [%4];"
        : "=r"(r[0]), "=r"(r[1]), "=r"(r[2]), "=r"(r[3]) : "r"(addr));
}

__device__ __forceinline__ void ldmx4t(uint32_t (&r)[4], uint32_t addr) {
    asm volatile("ldmatrix.sync.aligned.m8n8.x4.trans.shared.b16 {%0,%1,%2,%3}, [%4];"
        : "=r"(r[0]), "=r"(r[1]), "=r"(r[2]), "=r"(r[3]) : "r"(addr));
}

__device__ __forceinline__ void mma_fp16(float (&d)[4], const uint32_t (&a)[4],
                                         uint32_t b0, uint32_t b1) {
    asm volatile(
        "mma.sync.aligned.m16n8k16.row.col.f32.f16.f16.f32 "
        "{%0,%1,%2,%3}, {%4,%5,%6,%7}, {%8,%9}, {%0,%1,%2,%3};"
        : "+f"(d[0]), "+f"(d[1]), "+f"(d[2]), "+f"(d[3])
        : "r"(a[0]), "r"(a[1]), "r"(a[2]), "r"(a[3]), "r"(b0), "r"(b1));
}

__device__ __forceinline__ float gelu_exact(float x) {
    return 0.5f * x * (1.0f + erff(x * 0.70710678118654752f));
}

__device__ __forceinline__ void split_fp16(float v, half& hi, half& lo) {
    hi = __float2half(v);
    lo = __float2half(v - __half2float(hi));
}

__device__ __forceinline__ uint32_t pack_fp162(half a, half b) {
    half2 t = __halves2half2(a, b);
    uint32_t r;
    memcpy(&r, &t, 4);
    return r;
}

// Packed-pair SW128 swizzle for 128 logical rows x 64B tiles.
__device__ __forceinline__ uint32_t sw_off(int r, int c) {
    return (uint32_t)(((r >> 1) << 7) +
                      (((((r & 1) << 2) | c) ^ ((r >> 1) & 7)) << 4));
}

// ---------------------------------------------------------------------------
// Weight prep: W[R,C] fp32 -> WT [C,R] fp16, scaled by WSCALE
// ---------------------------------------------------------------------------
__global__ void wprep_kernel(const float* __restrict__ W, half* __restrict__ Th,
                             int R, int C) {
    __shared__ float t[32][33];
    int c0 = blockIdx.x * 32, r0 = blockIdx.y * 32;
    #pragma unroll
    for (int j = 0; j < 4; j++)
        t[threadIdx.y + j * 8][threadIdx.x] =
            W[(size_t)(r0 + threadIdx.y + j * 8) * C + c0 + threadIdx.x];
    __syncthreads();
    #pragma unroll
    for (int j = 0; j < 4; j++) {
        float v = t[threadIdx.x][threadIdx.y + j * 8] * WSCALE;
        size_t idx = (size_t)(c0 + threadIdx.y + j * 8) * R + r0 + threadIdx.x;
        Th[idx] = __float2half(v);
    }
}

__global__ void wprep3_kernel(const float* __restrict__ Wq,
                              const float* __restrict__ Wk,
                              const float* __restrict__ Wv,
                              half* __restrict__ Th) {
    __shared__ float t[32][33];
    const float* W = (blockIdx.z == 0) ? Wq : ((blockIdx.z == 1) ? Wk : Wv);
    half* Tho = Th + (size_t)blockIdx.z * EMBD * EMBD;
    int c0 = blockIdx.x * 32, r0 = blockIdx.y * 32;
    #pragma unroll
    for (int j = 0; j < 4; j++)
        t[threadIdx.y + j * 8][threadIdx.x] =
            W[(size_t)(r0 + threadIdx.y + j * 8) * EMBD + c0 + threadIdx.x];
    __syncthreads();
    #pragma unroll
    for (int j = 0; j < 4; j++) {
        float v = t[threadIdx.x][threadIdx.y + j * 8] * WSCALE;
        size_t idx = (size_t)(c0 + threadIdx.y + j * 8) * EMBD + r0 + threadIdx.x;
        Tho[idx] = __float2half(v);
    }
}

// ---------------------------------------------------------------------------
// LayerNorm -> fp16 hi/lo pair
// ---------------------------------------------------------------------------
__global__ void ln_pair_kernel(const float* __restrict__ x,
                               const float* __restrict__ g,
                               const float* __restrict__ beta,
                               half* __restrict__ yh, half* __restrict__ yl) {
    int row = blockIdx.x;
    int tid = threadIdx.x;
    const float4* xr = (const float4*)(x + (size_t)row * EMBD);
    float4 v = xr[tid];
    float s  = v.x + v.y + v.z + v.w;
    float ss = v.x*v.x + v.y*v.y + v.z*v.z + v.w*v.w;
    #pragma unroll
    for (int o = 16; o > 0; o >>= 1) {
        s  += __shfl_xor_sync(0xffffffffu, s,  o);
        ss += __shfl_xor_sync(0xffffffffu, ss, o);
    }
    __shared__ float sh[16];
    __shared__ float mean_s, rstd_s;
    int wid = tid >> 5, lane = tid & 31;
    if (lane == 0) { sh[wid] = s; sh[wid + 8] = ss; }
    __syncthreads();
    if (tid == 0) {
        float ts = 0.f, tss = 0.f;
        #pragma unroll
        for (int i = 0; i < 8; i++) { ts += sh[i]; tss += sh[i + 8]; }
        float mean = ts * (1.0f / EMBD);
        float var  = tss * (1.0f / EMBD) - mean * mean;
        mean_s = mean;
        rstd_s = rsqrtf(var + 1e-5f);
    }
    __syncthreads();
    float mean = mean_s, rstd = rstd_s;
    float4 gv = ((const float4*)g)[tid];
    float4 bv = ((const float4*)beta)[tid];
    float o[4];
    o[0] = (v.x - mean) * rstd * gv.x + bv.x;
    o[1] = (v.y - mean) * rstd * gv.y + bv.y;
    o[2] = (v.z - mean) * rstd * gv.z + bv.z;
    o[3] = (v.w - mean) * rstd * gv.w + bv.w;
    half2* yh2 = (half2*)(yh + (size_t)row * EMBD);
    half2* yl2 = (half2*)(yl + (size_t)row * EMBD);
    #pragma unroll
    for (int p = 0; p < 2; p++) {
        half h0, l0, h1, l1;
        split_fp16(o[p * 2 + 0], h0, l0);
        split_fp16(o[p * 2 + 1], h1, l1);
        yh2[tid * 2 + p] = __halves2half2(h0, h1);
        yl2[tid * 2 + p] = __halves2half2(l0, l1);
    }
}

// ---------------------------------------------------------------------------
// fp16x2 mma.sync GEMM — D = Ah*Bh + Al*Bh (R15 config: BK=32, 4-stage,
// packed SW128 smem, 98304 B + <=128 regs -> 2 CTAs/SM).
// ---------------------------------------------------------------------------
#define EPI_GELU 1
#define EPI_ADD  2
#define EPI_QKV  4

#define TILE_B 8192                   // 128 rows x 64B, packed 2-per-128B
#define OFF_AH 0
#define OFF_AL (1 * TILE_B)
#define OFF_BH (2 * TILE_B)
#define STAGE_B (3 * TILE_B)          // 24576
#define GEMM_SMEM (4 * STAGE_B)       // 98304

__device__ __forceinline__ void load_stage(
    uint32_t sdst, const half* __restrict__ Ah, const half* __restrict__ Al,
    const half* __restrict__ Bh,
    int row0, int col0, int k0, int K, int tid) {
    int r  = tid >> 2;            // 0..63
    int c  = tid & 3;             // 16B chunk
    int ch = c * 8;               // halves
    size_t a0 = (size_t)(row0 + r)      * K + k0 + ch;
    size_t a1 = (size_t)(row0 + r + 64) * K + k0 + ch;
    size_t b0 = (size_t)(col0 + r)      * K + k0 + ch;
    size_t b1 = (size_t)(col0 + r + 64) * K + k0 + ch;
    uint32_t d0 = sdst + sw_off(r, c);
    uint32_t d1 = sdst + sw_off(r + 64, c);
    cp_async16(d0 + OFF_AH, Ah + a0);
    cp_async16(d1 + OFF_AH, Ah + a1);
    cp_async16(d0 + OFF_AL, Al + a0);
    cp_async16(d1 + OFF_AL, Al + a1);
    cp_async16(d0 + OFF_BH, Bh + b0);
    cp_async16(d1 + OFF_BH, Bh + b1);
}

template <int EPI>
__global__ void __launch_bounds__(256, 2)
mma_gemm(const half* __restrict__ Ah, const half* __restrict__ Al,
         const half* __restrict__ Bh,
         const float* __restrict__ bias, const float* __restrict__ biasK,
         const float* __restrict__ biasV, const float* __restrict__ add,
         float* __restrict__ Cf, void* Chi_, void* Clo_,
         void* Ck_, void* Cv_,
         int M, int N, int K) {
    extern __shared__ char smem[];
    const uint32_t sb = smem_to_u32(smem);
    const int tid  = threadIdx.x;
    const int lane = tid & 31;
    const int warp = tid >> 5;
    const int wm = warp >> 2;
    const int wn = warp & 3;
    const int row0 = blockIdx.y * 128;
    const int col0 = blockIdx.x * 128;

    float acc[4][4][4];
    #pragma unroll
    for (int m = 0; m < 4; m++)
        #pragma unroll
        for (int n = 0; n < 4; n++)
            #pragma unroll
            for (int e = 0; e < 4; e++) acc[m][n][e] = 0.f;

    const int KT = K / 32;

    load_stage(sb, Ah, Al, Bh, row0, col0, 0, K, tid);
    cp_commit();
    load_stage(sb + STAGE_B, Ah, Al, Bh, row0, col0, 32, K, tid);
    cp_commit();
    load_stage(sb + 2 * STAGE_B, Ah, Al, Bh, row0, col0, 64, K, tid);
    cp_commit();

    // Per-lane swizzled ldmatrix base offsets.
    const int arow = wm * 64 + (lane & 15);
    const uint32_t a_base = (uint32_t)((arow >> 1) << 7);
    const uint32_t axk = (uint32_t)((arow >> 1) & 7);
    const uint32_t ae0 = (uint32_t)(((arow & 1) << 2) | (lane >> 4));
    const uint32_t a_ck[2] = { (ae0 ^ axk) << 4, ((ae0 + 2) ^ axk) << 4 };

    const int brow = wn * 32 + ((lane >> 4) << 3) + (lane & 7);
    const uint32_t b_base = (uint32_t)((brow >> 1) << 7);
    const uint32_t bxk = (uint32_t)((brow >> 1) & 7);
    const uint32_t be0 = (uint32_t)(((brow & 1) << 2) | ((lane >> 3) & 1));
    const uint32_t b_ck[2] = { (be0 ^ bxk) << 4, ((be0 + 2) ^ bxk) << 4 };

    for (int kt = 0; kt < KT; kt++) {
        if (kt + 1 < KT) cp_wait<2>(); else cp_wait<0>();
        __syncthreads();
        if (kt + 3 < KT) {
            load_stage(sb + ((kt + 3) & 3) * STAGE_B, Ah, Al, Bh,
                       row0, col0, (kt + 3) * 32, K, tid);
            cp_commit();
        }

        uint32_t s = sb + (kt & 3) * STAGE_B;
        #pragma unroll
        for (int ks = 0; ks < 2; ks++) {
            const uint32_t aoff = a_base + a_ck[ks];
            const uint32_t boff = b_base + b_ck[ks];
            uint32_t ah[4][4], al[4][4], bh[2][4];
            #pragma unroll
            for (int m = 0; m < 4; m++)
                ldmx4(ah[m], s + OFF_AH + aoff + m * 1024);
            #pragma unroll
            for (int m = 0; m < 4; m++)
                ldmx4(al[m], s + OFF_AL + aoff + m * 1024);
            #pragma unroll
            for (int n2 = 0; n2 < 2; n2++)
                ldmx4(bh[n2], s + OFF_BH + boff + n2 * 1024);

            #pragma unroll
            for (int m = 0; m < 4; m++)
                #pragma unroll
                for (int n = 0; n < 4; n++)
                    mma_fp16(acc[m][n], ah[m], bh[n >> 1][(n & 1) * 2],
                                               bh[n >> 1][(n & 1) * 2 + 1]);
            #pragma unroll
            for (int m = 0; m < 4; m++)
                #pragma unroll
                for (int n = 0; n < 4; n++)
                    mma_fp16(acc[m][n], al[m], bh[n >> 1][(n & 1) * 2],
                                               bh[n >> 1][(n & 1) * 2 + 1]);
        }
    }

    // Epilogue (acc carries WSCALE; undo before bias)
    const float* bseg = bias;
    int csub = 0;
    int seg = 0;
    if (EPI == EPI_QKV) {
        seg = col0 >> 10;
        bseg = (seg == 0) ? bias : ((seg == 1) ? biasK : biasV);
        csub = seg << 10;
    }
    const int erow = row0 + wm * 64 + (lane >> 2);
    const int ecol = col0 + wn * 32 + (lane & 3) * 2;
    #pragma unroll
    for (int m = 0; m < 4; m++) {
        #pragma unroll
        for (int n = 0; n < 4; n++) {
            int c = ecol + n * 8;
            float b0 = bseg[c - csub], b1 = bseg[c - csub + 1];
            #pragma unroll
            for (int half_i = 0; half_i < 2; half_i++) {
                int r = erow + m * 16 + half_i * 8;
                float v0 = acc[m][n][half_i * 2 + 0] * WSCALE_INV + b0;
                float v1 = acc[m][n][half_i * 2 + 1] * WSCALE_INV + b1;
                if (EPI == EPI_ADD) {
                    const float2 av = *(const float2*)&add[(size_t)r * N + c];
                    v0 += av.x; v1 += av.y;
                    float2 o; o.x = v0; o.y = v1;
                    *(float2*)&Cf[(size_t)r * N + c] = o;
                } else if (EPI == EPI_QKV) {
                    size_t oix = (size_t)r * EMBD + (c - csub);
                    if (seg == 0) {
                        // Q: pre-scale 1/8, hi/lo fp16 pair
                        v0 *= 0.125f;
                        v1 *= 0.125f;
                        half h0, l0, h1, l1;
                        split_fp16(v0, h0, l0);
                        split_fp16(v1, h1, l1);
                        *(half2*)&((half*)Chi_)[oix] = __halves2half2(h0, h1);
                        *(half2*)&((half*)Clo_)[oix] = __halves2half2(l0, l1);
                    } else if (seg == 1) {
                        *(half2*)&((half*)Ck_)[oix] =
                            __halves2half2(__float2half(v0), __float2half(v1));
                    } else {
                        *(half2*)&((half*)Cv_)[oix] =
                            __halves2half2(__float2half(v0), __float2half(v1));
                    }
                } else {   // EPI_GELU
                    v0 = gelu_exact(v0);
                    v1 = gelu_exact(v1);
                    half h0, l0, h1, l1;
                    split_fp16(v0, h0, l0);
                    split_fp16(v1, h1, l1);
                    half* Chi = (half*)Chi_;
                    half* Clo = (half*)Clo_;
                    *(half2*)&Chi[(size_t)r * N + c] = __halves2half2(h0, h1);
                    *(half2*)&Clo[(size_t)r * N + c] = __halves2half2(l0, l1);
                }
            }
        }
    }
}

// ---------------------------------------------------------------------------
// Flash attention, fp16x2: S = Qh·K + Ql·K, O = Ph·V + Pl·V (K,V single fp16).
// Grid (SEQ/64, NHEAD, BATCH), 128 threads (4 warps x 16 q-rows).
// ---------------------------------------------------------------------------
#define AT_TROW 144
#define AT_QH   0
#define AT_QL   9216
#define AT_KV0  18432
#define AT_STAGE 18432                // K 9216 + V 9216
#define AT_SMEM (18432 + 2 * 18432)   // 55296

__device__ __forceinline__ void attn_load_kv(
    uint32_t sb, int b, int h, const half* __restrict__ Kh,
    const half* __restrict__ Vh, int kt, int stage, int tid) {
    int kb = kt * 64;
    #pragma unroll
    for (int i = 0; i < 4; i++) {
        int c = tid + i * 128;
        int r = c >> 3, sg = c & 7;
        size_t g = (size_t)(b * SEQ + kb + r) * EMBD + h * HDIM + sg * 8;
        uint32_t d = sb + AT_KV0 + stage * AT_STAGE + r * AT_TROW + sg * 16;
        cp_async16(d,        Kh + g);
        cp_async16(d + 9216, Vh + g);
    }
}

__global__ void __launch_bounds__(128)
fattn_kernel(const half* __restrict__ Qh, const half* __restrict__ Ql,
             const half* __restrict__ Kh, const half* __restrict__ Vh,
             half* __restrict__ Oh, half* __restrict__ Ol) {
    extern __shared__ char smem[];
    const uint32_t sb = smem_to_u32(smem);
    const int tid = threadIdx.x;
    const int lane = tid & 31;
    const int wm = tid >> 5;
    const int qt = blockIdx.x;
    const int h  = blockIdx.y;
    const int b  = blockIdx.z;
    const int q0 = qt * 64;
    const int qrow0 = q0 + wm * 16 + (lane >> 2);
    const int qrow1 = qrow0 + 8;

    #pragma unroll
    for (int i = 0; i < 4; i++) {
        int c = tid + i * 128;
        int r = c >> 3, sg = c & 7;
        size_t g = (size_t)(b * SEQ + q0 + r) * EMBD + h * HDIM + sg * 8;
        cp_async16(sb + AT_QH + r * AT_TROW + sg * 16, Qh + g);
        cp_async16(sb + AT_QL + r * AT_TROW + sg * 16, Ql + g);
    }
    attn_load_kv(sb, b, h, Kh, Vh, 0, 0, tid);
    cp_commit();

    float m0 = -1e30f, m1 = -1e30f, l0 = 0.f, l1 = 0.f;
    float acc[8][4];
    #pragma unroll
    for (int j = 0; j < 8; j++)
        #pragma unroll
        for (int e = 0; e < 4; e++) acc[j][e] = 0.f;

    uint32_t qhf[4][4], qlf[4][4];
    const int ntiles = qt + 1;
    const int ce = (lane & 3) * 2;

    for (int kt = 0; kt < ntiles; kt++) {
        if (kt + 1 < ntiles) {
            attn_load_kv(sb, b, h, Kh, Vh, kt + 1, (kt + 1) & 1, tid);
            cp_commit();
            cp_wait<1>();
        } else {
            cp_wait<0>();
        }
        __syncthreads();

        if (kt == 0) {
            uint32_t qa = sb + AT_QH + (wm * 16 + (lane & 15)) * AT_TROW + (lane >> 4) * 16;
            #pragma unroll
            for (int ks = 0; ks < 4; ks++) {
                ldmx4(qhf[ks], qa + ks * 32);
                ldmx4(qlf[ks], qa + 9216 + ks * 32);
            }
        }

        const uint32_t sK = sb + AT_KV0 + (kt & 1) * AT_STAGE;
        const uint32_t sV = sK + 9216;

        // ---- S = Qh·K + Ql·K ----
        float c[8][4];
        #pragma unroll
        for (int j = 0; j < 8; j++)
            #pragma unroll
            for (int e = 0; e < 4; e++) c[j][e] = 0.f;

        const uint32_t bb = (((lane >> 4) << 3) + (lane & 7)) * AT_TROW
                            + ((lane >> 3) & 1) * 16;
        #pragma unroll
        for (int ks = 0; ks < 4; ks++) {
            uint32_t kbh[4][4];
            #pragma unroll
            for (int nn = 0; nn < 4; nn++)
                ldmx4(kbh[nn], sK + nn * 16 * AT_TROW + bb + ks * 32);
            #pragma unroll
            for (int j = 0; j < 8; j++) {
                uint32_t h0 = kbh[j >> 1][(j & 1) * 2], h1 = kbh[j >> 1][(j & 1) * 2 + 1];
                mma_fp16(c[j], qhf[ks], h0, h1);
                mma_fp16(c[j], qlf[ks], h0, h1);
            }
        }

        // ---- mask + online softmax ----
        const int kb = kt * 64;
        float tmax0 = -1e30f, tmax1 = -1e30f;
        #pragma unroll
        for (int j = 0; j < 8; j++) {
            int ka = kb + j * 8 + ce;
            int kc = ka + 1;
            bool okA = ((ka + 1) % JOINED != 0);
            bool okB = ((kc + 1) % JOINED != 0);
            float s0 = (okA && ka <= qrow0) ? c[j][0] : -1e30f;
            float s1 = (okB && kc <= qrow0) ? c[j][1] : -1e30f;
            float s2 = (okA && ka <= qrow1) ? c[j][2] : -1e30f;
            float s3 = (okB && kc <= qrow1) ? c[j][3] : -1e30f;
            c[j][0] = s0; c[j][1] = s1; c[j][2] = s2; c[j][3] = s3;
            tmax0 = fmaxf(tmax0, fmaxf(s0, s1));
            tmax1 = fmaxf(tmax1, fmaxf(s2, s3));
        }
        tmax0 = fmaxf(tmax0, __shfl_xor_sync(0xffffffffu, tmax0, 1));
        tmax0 = fmaxf(tmax0, __shfl_xor_sync(0xffffffffu, tmax0, 2));
        tmax1 = fmaxf(tmax1, __shfl_xor_sync(0xffffffffu, tmax1, 1));
        tmax1 = fmaxf(tmax1, __shfl_xor_sync(0xffffffffu, tmax1, 2));
        float mn0 = fmaxf(m0, tmax0), mn1 = fmaxf(m1, tmax1);
        float cr0 = __expf(m0 - mn0), cr1 = __expf(m1 - mn1);
        m0 = mn0; m1 = mn1;

        uint32_t pah[4][4], pal[4][4];
        float ps0 = 0.f, ps1 = 0.f;
        #pragma unroll
        for (int j = 0; j < 8; j++) {
            float p0 = __expf(c[j][0] - mn0);
            float p1 = __expf(c[j][1] - mn0);
            float p2 = __expf(c[j][2] - mn1);
            float p3 = __expf(c[j][3] - mn1);
            ps0 += p0 + p1;
            ps1 += p2 + p3;
            half h0, lo0, h1, lo1, h2, lo2, h3, lo3;
            split_fp16(p0, h0, lo0); split_fp16(p1, h1, lo1);
            split_fp16(p2, h2, lo2); split_fp16(p3, h3, lo3);
            int t = j >> 1, rr = (j & 1) * 2;
            pah[t][rr]     = pack_fp162(h0, h1);
            pah[t][rr + 1] = pack_fp162(h2, h3);
            pal[t][rr]     = pack_fp162(lo0, lo1);
            pal[t][rr + 1] = pack_fp162(lo2, lo3);
        }
        l0 = l0 * cr0 + ps0;
        l1 = l1 * cr1 + ps1;
        #pragma unroll
        for (int j = 0; j < 8; j++) {
            acc[j][0] *= cr0; acc[j][1] *= cr0;
            acc[j][2] *= cr1; acc[j][3] *= cr1;
        }

        // ---- O += Ph·V + Pl·V ----
        const uint32_t vrow = (lane & 7) + ((lane >> 3) & 1) * 8;
        const uint32_t vcb  = (lane >> 4) * 16;
        #pragma unroll
        for (int t = 0; t < 4; t++) {
            uint32_t vbh[4][4];
            uint32_t vb = sV + (t * 16 + vrow) * AT_TROW + vcb;
            #pragma unroll
            for (int jj = 0; jj < 4; jj++)
                ldmx4t(vbh[jj], vb + jj * 32);
            #pragma unroll
            for (int jj = 0; jj < 4; jj++) {
                mma_fp16(acc[2 * jj],     pah[t], vbh[jj][0], vbh[jj][1]);
                mma_fp16(acc[2 * jj + 1], pah[t], vbh[jj][2], vbh[jj][3]);
                mma_fp16(acc[2 * jj],     pal[t], vbh[jj][0], vbh[jj][1]);
                mma_fp16(acc[2 * jj + 1], pal[t], vbh[jj][2], vbh[jj][3]);
            }
        }
        __syncthreads();
    }

    l0 += __shfl_xor_sync(0xffffffffu, l0, 1);
    l0 += __shfl_xor_sync(0xffffffffu, l0, 2);
    l1 += __shfl_xor_sync(0xffffffffu, l1, 1);
    l1 += __shfl_xor_sync(0xffffffffu, l1, 2);
    float inv0 = 1.0f / l0, inv1 = 1.0f / l1;
    size_t o0 = (size_t)(b * SEQ + qrow0) * EMBD + h * HDIM;
    size_t o1 = (size_t)(b * SEQ + qrow1) * EMBD + h * HDIM;
    #pragma unroll
    for (int j = 0; j < 8; j++) {
        int cc = j * 8 + ce;
        float v0 = acc[j][0] * inv0, v1 = acc[j][1] * inv0;
        float v2 = acc[j][2] * inv1, v3 = acc[j][3] * inv1;
        half h0, lo0, h1, lo1, h2, lo2, h3, lo3;
        split_fp16(v0, h0, lo0); split_fp16(v1, h1, lo1);
        split_fp16(v2, h2, lo2); split_fp16(v3, h3, lo3);
        *(half2*)&Oh[o0 + cc] = __halves2half2(h0, h1);
        *(half2*)&Ol[o0 + cc] = __halves2half2(lo0, lo1);
        *(half2*)&Oh[o1 + cc] = __halves2half2(h2, h3);
        *(half2*)&Ol[o1 + cc] = __halves2half2(lo2, lo3);
    }
}

// ---------------------------------------------------------------------------
// Host launcher
// ---------------------------------------------------------------------------
extern "C" void kernel_launch(void* const* d_in, const int* in_sizes, int n_in,
                              void* d_out, int out_size) {
    const float* hidden = (const float*)d_in[0];
    const float* Wq = (const float*)d_in[1];
    const float* bq = (const float*)d_in[2];
    const float* Wk = (const float*)d_in[3];
    const float* bk = (const float*)d_in[4];
    const float* Wv = (const float*)d_in[5];
    const float* bv = (const float*)d_in[6];
    const float* Wp = (const float*)d_in[7];
    const float* bp = (const float*)d_in[8];
    const float* ln1_g = (const float*)d_in[9];
    const float* ln1_b = (const float*)d_in[10];
    const float* ln2_g = (const float*)d_in[11];
    const float* ln2_b = (const float*)d_in[12];
    const float* W1 = (const float*)d_in[13];
    const float* b1 = (const float*)d_in[14];
    const float* W2 = (const float*)d_in[15];
    const float* b2 = (const float*)d_in[16];
    float* out = (float*)d_out;

    float *h1;
    half *xlnh, *xlnl, *abh, *abl, *x2h, *x2l, *mhh, *mhl;
    half *qh, *ql, *kh, *vh;
    half *wqkvh, *wph, *w1h, *w2h;
    cudaGetSymbolAddress((void**)&h1,  g_h1);
    cudaGetSymbolAddress((void**)&xlnh, g_xlnh);
    cudaGetSymbolAddress((void**)&xlnl, g_xlnl);
    cudaGetSymbolAddress((void**)&qh, g_qh);
    cudaGetSymbolAddress((void**)&ql, g_ql);
    cudaGetSymbolAddress((void**)&kh, g_kh);
    cudaGetSymbolAddress((void**)&vh, g_vh);
    cudaGetSymbolAddress((void**)&abh, g_abh);
    cudaGetSymbolAddress((void**)&abl, g_abl);
    cudaGetSymbolAddress((void**)&x2h, g_x2h);
    cudaGetSymbolAddress((void**)&x2l, g_x2l);
    cudaGetSymbolAddress((void**)&mhh, g_mhh);
    cudaGetSymbolAddress((void**)&mhl, g_mhl);
    cudaGetSymbolAddress((void**)&wqkvh, g_wqkvh);
    cudaGetSymbolAddress((void**)&wph, g_wph);
    cudaGetSymbolAddress((void**)&w1h, g_w1h);
    cudaGetSymbolAddress((void**)&w2h, g_w2h);

    cudaFuncSetAttribute(mma_gemm<EPI_QKV>,
                         cudaFuncAttributeMaxDynamicSharedMemorySize, GEMM_SMEM);
    cudaFuncSetAttribute(mma_gemm<EPI_ADD>,
                         cudaFuncAttributeMaxDynamicSharedMemorySize, GEMM_SMEM);
    cudaFuncSetAttribute(mma_gemm<EPI_GELU>,
                         cudaFuncAttributeMaxDynamicSharedMemorySize, GEMM_SMEM);
    cudaFuncSetAttribute(fattn_kernel,
                         cudaFuncAttributeMaxDynamicSharedMemorySize, AT_SMEM);

    dim3 tb(32, 8);

    // 0. LN1
    ln_pair_kernel<<<MROWS, 256>>>(hidden, ln1_g, ln1_b, xlnh, xlnl);

    // 1. Fused QKV weight prep (fp16, scaled)
    wprep3_kernel<<<dim3(EMBD/32, EMBD/32, 3), tb>>>(Wq, Wk, Wv, wqkvh);

    // 2. Wp prep
    wprep_kernel<<<dim3(EMBD/32, EMBD/32), tb>>>(Wp, wph, EMBD, EMBD);

    // 3. Fused QKV projection -> Q pair (scaled 1/8), K single, V single
    dim3 grid_qkv(QKVN / 128, MROWS / 128);
    mma_gemm<EPI_QKV><<<grid_qkv, 256, GEMM_SMEM>>>(xlnh, xlnl, wqkvh,
                                                    bq, bk, bv, nullptr,
                                                    nullptr, qh, ql, kh, vh,
                                                    MROWS, QKVN, EMBD);

    // 4. Flash attention (fp16x2) -> fp16 pairs
    dim3 agrid(SEQ / 64, NHEAD, BATCH);
    fattn_kernel<<<agrid, 128, AT_SMEM>>>(qh, ql, kh, vh, abh, abl);

    // 5. Output projection + residual -> h1 (fp32)
    dim3 grid_d(EMBD / 128, MROWS / 128);
    mma_gemm<EPI_ADD><<<grid_d, 256, GEMM_SMEM>>>(abh, abl, wph,
                                                  bp, nullptr, nullptr, hidden,
                                                  h1, nullptr, nullptr, nullptr, nullptr,
                                                  MROWS, EMBD, EMBD);

    // 6-7. MLP weight preps
    wprep_kernel<<<dim3(FFN/32,  EMBD/32), tb>>>(W1, w1h, EMBD, FFN);
    wprep_kernel<<<dim3(EMBD/32, FFN/32),  tb>>>(W2, w2h, FFN, EMBD);

    // 8. LN2
    ln_pair_kernel<<<MROWS, 256>>>(h1, ln2_g, ln2_b, x2h, x2l);

    // 9. MLP up + GELU -> fp16 pairs
    dim3 grid_f(FFN / 128, MROWS / 128);
    mma_gemm<EPI_GELU><<<grid_f, 256, GEMM_SMEM>>>(x2h, x2l, w1h,
                                                   b1, nullptr, nullptr, nullptr,
                                                   nullptr, mhh, mhl, nullptr, nullptr,
                                                   MROWS, FFN, EMBD);

    // 10. MLP down + residual2 -> out
    mma_gemm<EPI_ADD><<<grid_d, 256, GEMM_SMEM>>>(mhh, mhl, w2h,
                                                  b2, nullptr, nullptr, h1,
                                                  out, nullptr, nullptr, nullptr, nullptr,
                                                  MROWS, EMBD, FFN);
}